// round 8
// baseline (speedup 1.0000x reference)
#include <cuda_runtime.h>
#include <cstdint>

#define VOCAB 100000
#define EMBED 64
#define NPOS  51200          // B*S = 1024*50
#define KIDS  20

// W transposed to [VOCAB, EMBED]: each id gather = 256B contiguous. 25.6MB, L2-resident.
__device__ __align__(16) float g_WT[(size_t)VOCAB * EMBED];

__device__ __forceinline__ void addf32x2(unsigned long long& a, unsigned long long b) {
    asm("add.rn.f32x2 %0, %0, %1;" : "+l"(a) : "l"(b));
}

// ---------------------------------------------------------------------------
// Kernel 1: transpose W[64, 100000] -> g_WT[100000, 64]. float4 both ways.
// Tile: 32 (V) x 64 (E, full). Grid = 100000/32 = 3125 blocks of 256 threads.
// ---------------------------------------------------------------------------
__global__ __launch_bounds__(256) void transpose_W_kernel(const float* __restrict__ W) {
    __shared__ float tile[64][33];
    const int tid = threadIdx.x;
    const int v0  = blockIdx.x * 32;

    // Load: 64 rows x 8 float4 (32 floats) = 512 float4, 2 per thread.
    // Per-warp: 4 rows x 128B contiguous -> full sectors.
    #pragma unroll
    for (int i = 0; i < 2; ++i) {
        int j  = tid + i * 256;
        int e  = j >> 3;
        int vq = (j & 7) * 4;
        float4 val = *reinterpret_cast<const float4*>(W + (size_t)e * VOCAB + v0 + vq);
        tile[e][vq + 0] = val.x;
        tile[e][vq + 1] = val.y;
        tile[e][vq + 2] = val.z;
        tile[e][vq + 3] = val.w;
    }
    __syncthreads();

    // Store: 32 v-rows x 16 float4 (64 floats) = 512 float4, 2 per thread.
    // Per-warp global store = 512B fully contiguous.
    #pragma unroll
    for (int i = 0; i < 2; ++i) {
        int j  = tid + i * 256;
        int v  = j >> 4;
        int e4 = (j & 15) * 4;
        float4 o = make_float4(tile[e4 + 0][v], tile[e4 + 1][v],
                               tile[e4 + 2][v], tile[e4 + 3][v]);
        *reinterpret_cast<float4*>(g_WT + (size_t)(v0 + v) * EMBED + e4) = o;
    }
}

// ---------------------------------------------------------------------------
// Kernel 2: embedding-bag gather. 16 lanes per position (float4 each),
// 2 positions per warp, 16 positions per 256-thread block.
// Ids staged in SMEM (no shuffles). Packed f32x2 adds, 2 acc chains.
// ---------------------------------------------------------------------------
__global__ __launch_bounds__(256) void gather_sum_kernel(
    const int*   __restrict__ ids,    // [NPOS, KIDS]
    const float* __restrict__ bias,   // [EMBED]
    float*       __restrict__ out)    // [NPOS, EMBED]
{
    __shared__ int sids[16 * KIDS];   // 320 ids for this block's 16 positions

    const int tid  = threadIdx.x;
    const int pos0 = blockIdx.x * 16;

    // Coalesced cooperative id load (320 ints = 1280B).
    #pragma unroll
    for (int i = tid; i < 16 * KIDS; i += 256)
        sids[i] = ids[(size_t)pos0 * KIDS + i];
    __syncthreads();

    const int p   = tid >> 4;         // local position 0..15
    const int sub = tid & 15;         // owns floats [4*sub, 4*sub+4)
    const int* myids = sids + p * KIDS;
    const float* wt  = g_WT + (size_t)sub * 4;

    unsigned long long a0 = 0, a1 = 0, b0 = 0, b1 = 0;  // 0ull == {0.f,0.f}

    #pragma unroll
    for (int k = 0; k < KIDS; k += 2) {
        ulonglong2 w0 = *reinterpret_cast<const ulonglong2*>(wt + (size_t)myids[k]     * EMBED);
        ulonglong2 w1 = *reinterpret_cast<const ulonglong2*>(wt + (size_t)myids[k + 1] * EMBED);
        addf32x2(a0, w0.x); addf32x2(a1, w0.y);
        addf32x2(b0, w1.x); addf32x2(b1, w1.y);
    }
    addf32x2(a0, b0);
    addf32x2(a1, b1);

    ulonglong2 bb = *reinterpret_cast<const ulonglong2*>(bias + sub * 4);
    addf32x2(a0, bb.x);
    addf32x2(a1, bb.y);

    ulonglong2 r;
    r.x = a0;
    r.y = a1;
    *reinterpret_cast<ulonglong2*>(out + (size_t)(pos0 + p) * EMBED + sub * 4) = r;
}

// ---------------------------------------------------------------------------
// inputs: 0 = content_input int32 [B,S,K], 1 = W f32 [E,V], 2 = b f32 [E]
// output: f32 [B,S,E]
// ---------------------------------------------------------------------------
extern "C" void kernel_launch(void* const* d_in, const int* in_sizes, int n_in,
                              void* d_out, int out_size) {
    const int*   ids  = (const int*)d_in[0];
    const float* W    = (const float*)d_in[1];
    const float* bias = (const float*)d_in[2];
    float*       out  = (float*)d_out;

    transpose_W_kernel<<<VOCAB / 32, 256>>>(W);          // 3125 blocks
    gather_sum_kernel<<<NPOS / 16, 256>>>(ids, bias, out); // 3200 blocks
}

// round 9
// speedup vs baseline: 1.1913x; 1.1913x over previous
#include <cuda_runtime.h>
#include <cuda_fp16.h>
#include <cstdint>

#define VOCAB 100000
#define EMBED 64
#define NPOS  51200          // B*S = 1024*50
#define KIDS  20

// W transposed + converted to fp16: [VOCAB, EMBED] = 12.8 MB, L2-resident.
// Each id gather = 128B contiguous (4 full sectors, zero waste).
__device__ __align__(16) __half g_WTh[(size_t)VOCAB * EMBED];

// ---------------------------------------------------------------------------
// Kernel 1: transpose + convert  W[64, 100000] f32  ->  g_WTh[100000, 64] f16
// Tile: 32 (V) x 64 (E, full). Grid = 100000/32 = 3125 blocks of 256 threads.
// ---------------------------------------------------------------------------
__global__ __launch_bounds__(256) void transpose_W_kernel(const float* __restrict__ W) {
    __shared__ float tile[64][33];
    const int tid = threadIdx.x;
    const int v0  = blockIdx.x * 32;

    // Load: 64 E-rows x 8 float4 = 512 float4, 2 per thread. 128B/warp-quad, coalesced.
    #pragma unroll
    for (int i = 0; i < 2; ++i) {
        int j  = tid + i * 256;
        int e  = j >> 3;
        int vq = (j & 7) * 4;
        float4 val = *reinterpret_cast<const float4*>(W + (size_t)e * VOCAB + v0 + vq);
        tile[e][vq + 0] = val.x;
        tile[e][vq + 1] = val.y;
        tile[e][vq + 2] = val.z;
        tile[e][vq + 3] = val.w;
    }
    __syncthreads();

    // Store: 32 V-rows x 64 halves (128B/row) = 32 x 8 uint4. Thread j writes
    // 8 halves: v = j>>3, e8 = (j&7)*8. Smem reads are conflict-free
    // (8*(e8/8)+v mod 32 covers all 32 banks per access phase).
    {
        int v  = tid >> 3;
        int e8 = (tid & 7) * 8;
        __half2 h[4];
        #pragma unroll
        for (int i = 0; i < 4; ++i) {
            h[i] = __floats2half2_rn(tile[e8 + 2 * i][v], tile[e8 + 2 * i + 1][v]);
        }
        *reinterpret_cast<uint4*>(g_WTh + (size_t)(v0 + v) * EMBED + e8) =
            *reinterpret_cast<uint4*>(h);
    }
}

// ---------------------------------------------------------------------------
// Kernel 2: embedding-bag gather. 8 lanes per position, each lane does one
// LDG.128 (8 halves) per id -> 8 lanes x 16B = full 128B row. 32 positions
// per 256-thread block. fp32 accumulation, ids staged in SMEM.
// ---------------------------------------------------------------------------
__global__ __launch_bounds__(256) void gather_sum_kernel(
    const int*   __restrict__ ids,    // [NPOS, KIDS]
    const float* __restrict__ bias,   // [EMBED]
    float*       __restrict__ out)    // [NPOS, EMBED]
{
    __shared__ int sids[32 * KIDS];   // 640 ids for this block's 32 positions

    const int tid  = threadIdx.x;
    const int pos0 = blockIdx.x * 32;

    // Coalesced cooperative id load (640 ints = 2560B).
    #pragma unroll
    for (int i = tid; i < 32 * KIDS; i += 256)
        sids[i] = ids[(size_t)pos0 * KIDS + i];
    __syncthreads();

    const int p   = tid >> 3;         // local position 0..31
    const int sub = tid & 7;          // owns embed elems [8*sub, 8*sub+8)
    const int* myids = sids + p * KIDS;
    const __half* wt = g_WTh + (size_t)sub * 8;

    float acc[8];
    #pragma unroll
    for (int i = 0; i < 8; ++i) acc[i] = 0.f;

    #pragma unroll
    for (int k = 0; k < KIDS; ++k) {
        uint4 raw = *reinterpret_cast<const uint4*>(wt + (size_t)myids[k] * EMBED);
        const __half2* h = reinterpret_cast<const __half2*>(&raw);
        #pragma unroll
        for (int i = 0; i < 4; ++i) {
            float2 f = __half22float2(h[i]);
            acc[2 * i]     += f.x;
            acc[2 * i + 1] += f.y;
        }
    }

    // Bias (fp32, exact) + output write: 8 floats = two float4, 256B/position.
    const float4 b0 = __ldg(reinterpret_cast<const float4*>(bias + sub * 8));
    const float4 b1 = __ldg(reinterpret_cast<const float4*>(bias + sub * 8 + 4));

    float4 r0 = make_float4(acc[0] + b0.x, acc[1] + b0.y, acc[2] + b0.z, acc[3] + b0.w);
    float4 r1 = make_float4(acc[4] + b1.x, acc[5] + b1.y, acc[6] + b1.z, acc[7] + b1.w);

    float* op = out + (size_t)(pos0 + p) * EMBED + sub * 8;
    *reinterpret_cast<float4*>(op)     = r0;
    *reinterpret_cast<float4*>(op + 4) = r1;
}

// ---------------------------------------------------------------------------
// inputs: 0 = content_input int32 [B,S,K], 1 = W f32 [E,V], 2 = b f32 [E]
// output: f32 [B,S,E]
// ---------------------------------------------------------------------------
extern "C" void kernel_launch(void* const* d_in, const int* in_sizes, int n_in,
                              void* d_out, int out_size) {
    const int*   ids  = (const int*)d_in[0];
    const float* W    = (const float*)d_in[1];
    const float* bias = (const float*)d_in[2];
    float*       out  = (float*)d_out;

    transpose_W_kernel<<<VOCAB / 32, 256>>>(W);            // 3125 blocks
    gather_sum_kernel<<<NPOS / 32, 256>>>(ids, bias, out); // 1600 blocks
}

// round 10
// speedup vs baseline: 1.2302x; 1.0327x over previous
#include <cuda_runtime.h>
#include <cuda_fp16.h>
#include <cstdint>

#define VOCAB 100000
#define EMBED 64
#define NPOS  51200          // B*S = 1024*50
#define KIDS  20

// W transposed + converted to fp16: [VOCAB, EMBED] = 12.8 MB, L2-resident.
// Each id gather = 128B contiguous (4 full sectors, zero waste).
__device__ __align__(16) __half g_WTh[(size_t)VOCAB * EMBED];

// ---------------------------------------------------------------------------
// Kernel 1: transpose + convert  W[64, 100000] f32  ->  g_WTh[100000, 64] f16
// Tile: 32 (V) x 64 (E, full). Grid = 100000/32 = 3125 blocks of 256 threads.
// ---------------------------------------------------------------------------
__global__ __launch_bounds__(256) void transpose_W_kernel(const float* __restrict__ W) {
    __shared__ float tile[64][33];
    const int tid = threadIdx.x;
    const int v0  = blockIdx.x * 32;

    // Load: 64 E-rows x 8 float4 = 512 float4, 2 per thread, coalesced.
    #pragma unroll
    for (int i = 0; i < 2; ++i) {
        int j  = tid + i * 256;
        int e  = j >> 3;
        int vq = (j & 7) * 4;
        float4 val = *reinterpret_cast<const float4*>(W + (size_t)e * VOCAB + v0 + vq);
        tile[e][vq + 0] = val.x;
        tile[e][vq + 1] = val.y;
        tile[e][vq + 2] = val.z;
        tile[e][vq + 3] = val.w;
    }
    __syncthreads();

    // Store: 32 V-rows x 64 halves (128B/row). Thread: v = tid>>3, e8 = (tid&7)*8.
    {
        int v  = tid >> 3;
        int e8 = (tid & 7) * 8;
        __half2 h[4];
        #pragma unroll
        for (int i = 0; i < 4; ++i) {
            h[i] = __floats2half2_rn(tile[e8 + 2 * i][v], tile[e8 + 2 * i + 1][v]);
        }
        *reinterpret_cast<uint4*>(g_WTh + (size_t)(v0 + v) * EMBED + e8) =
            *reinterpret_cast<uint4*>(h);
    }
}

// ---------------------------------------------------------------------------
// Kernel 2: embedding-bag gather, split-K.
// 16 lanes per position: (sub = tid&7 owns a 16B slice of the 128B row,
// h = (tid>>3)&1 handles ids k = 2j+h, j=0..9). Each thread: 10 independent
// LDG.128 -> deep MLP. One shfl_xor(8) round merges the h halves; h==0 lanes
// add bias and store. 16 positions per 256-thread block.
// ---------------------------------------------------------------------------
__global__ __launch_bounds__(256) void gather_sum_kernel(
    const int*   __restrict__ ids,    // [NPOS, KIDS]
    const float* __restrict__ bias,   // [EMBED]
    float*       __restrict__ out)    // [NPOS, EMBED]
{
    __shared__ int sids[16 * KIDS];   // 320 ids for this block's 16 positions

    const int tid  = threadIdx.x;
    const int pos0 = blockIdx.x * 16;

    // Coalesced cooperative id load (320 ints = 1280B).
    for (int i = tid; i < 16 * KIDS; i += 256)
        sids[i] = ids[(size_t)pos0 * KIDS + i];
    __syncthreads();

    const int p   = tid >> 4;         // local position 0..15
    const int sub = tid & 7;          // 16B slice: embed elems [8*sub, 8*sub+8)
    const int h   = (tid >> 3) & 1;   // K-split half
    const int* myids = sids + p * KIDS;
    const __half* wt = g_WTh + (size_t)sub * 8;

    float acc[8];
    #pragma unroll
    for (int i = 0; i < 8; ++i) acc[i] = 0.f;

    // 10 independent 16B loads per thread (ids pre-read to break dependence).
    int  kid[10];
    #pragma unroll
    for (int j = 0; j < 10; ++j) kid[j] = myids[2 * j + h];

    #pragma unroll
    for (int j = 0; j < 10; ++j) {
        uint4 raw = *reinterpret_cast<const uint4*>(wt + (size_t)kid[j] * EMBED);
        const __half2* hp = reinterpret_cast<const __half2*>(&raw);
        #pragma unroll
        for (int i = 0; i < 4; ++i) {
            float2 f = __half22float2(hp[i]);
            acc[2 * i]     += f.x;
            acc[2 * i + 1] += f.y;
        }
    }

    // Merge the two K-halves: partner lane differs by bit 3 (same position,
    // since each position occupies 16 consecutive lanes).
    #pragma unroll
    for (int i = 0; i < 8; ++i)
        acc[i] += __shfl_xor_sync(0xffffffffu, acc[i], 8);

    if (h == 0) {
        const float4 b0 = __ldg(reinterpret_cast<const float4*>(bias + sub * 8));
        const float4 b1 = __ldg(reinterpret_cast<const float4*>(bias + sub * 8 + 4));

        float4 r0 = make_float4(acc[0] + b0.x, acc[1] + b0.y, acc[2] + b0.z, acc[3] + b0.w);
        float4 r1 = make_float4(acc[4] + b1.x, acc[5] + b1.y, acc[6] + b1.z, acc[7] + b1.w);

        float* op = out + (size_t)(pos0 + p) * EMBED + sub * 8;
        *reinterpret_cast<float4*>(op)     = r0;
        *reinterpret_cast<float4*>(op + 4) = r1;
    }
}

// ---------------------------------------------------------------------------
// inputs: 0 = content_input int32 [B,S,K], 1 = W f32 [E,V], 2 = b f32 [E]
// output: f32 [B,S,E]
// ---------------------------------------------------------------------------
extern "C" void kernel_launch(void* const* d_in, const int* in_sizes, int n_in,
                              void* d_out, int out_size) {
    const int*   ids  = (const int*)d_in[0];
    const float* W    = (const float*)d_in[1];
    const float* bias = (const float*)d_in[2];
    float*       out  = (float*)d_out;

    transpose_W_kernel<<<VOCAB / 32, 256>>>(W);            // 3125 blocks
    gather_sum_kernel<<<NPOS / 16, 256>>>(ids, bias, out); // 3200 blocks
}